// round 9
// baseline (speedup 1.0000x reference)
#include <cuda_runtime.h>
#include <cuda_fp16.h>
#include <cstdint>
#include <cstddef>

#define NN 50000
#define NE 800000
#define NHH 8

__device__ __align__(16) __half g_xW  [(size_t)NN * 128];
__device__ __align__(16) __half g_preA[(size_t)NN * 128];
__device__ __align__(16) __half g_preB[(size_t)NN * 128];
__device__ __align__(16) __half g_msg [(size_t)NE * 128];
__device__ __align__(16) float  g_a   [(size_t)NE * 8];
__device__ __align__(16) float  g_agg [(size_t)NN * 128];
__device__ float g_maxh[NHH];
__device__ float g_sumh[NHH];

__device__ __forceinline__ float silu_f(float x) { return __fdividef(x, 1.0f + __expf(-x)); }

__device__ __forceinline__ void atomicMaxF(float* addr, float val) {
    int old = __float_as_int(*addr);
    while (__int_as_float(old) < val) {
        int assumed = old;
        old = atomicCAS((int*)addr, assumed, __float_as_int(val));
        if (old == assumed) break;
    }
}

__device__ __forceinline__ uint32_t smem_u32(const void* p) {
    uint32_t a;
    asm("{ .reg .u64 t; cvta.to.shared.u64 t, %1; cvt.u32.u64 %0, t; }" : "=r"(a) : "l"(p));
    return a;
}

__device__ __forceinline__ uint32_t packh2(float a, float b) {
    __half2 h = __floats2half2_rn(a, b);
    return *reinterpret_cast<uint32_t*>(&h);
}
__device__ __forceinline__ float2 unpackh2(uint32_t u) {
    return __half22float2(*reinterpret_cast<__half2*>(&u));
}
__device__ __forceinline__ uint32_t packh2_f2(float2 v) { return packh2(v.x, v.y); }

// m16n8k16 row.col f16 x f16 -> f16 accum
__device__ __forceinline__ void mmah(uint32_t* c, const uint32_t* a, uint32_t b0, uint32_t b1) {
    asm volatile("mma.sync.aligned.m16n8k16.row.col.f16.f16.f16.f16 "
                 "{%0,%1}, {%2,%3,%4,%5}, {%6,%7}, {%0,%1};"
                 : "+r"(c[0]), "+r"(c[1])
                 : "r"(a[0]), "r"(a[1]), "r"(a[2]), "r"(a[3]), "r"(b0), "r"(b1));
}

__device__ __forceinline__ void ldmat4(uint32_t& r0, uint32_t& r1, uint32_t& r2, uint32_t& r3,
                                       uint32_t saddr) {
    asm volatile("ldmatrix.sync.aligned.m8n8.x4.shared.b16 {%0,%1,%2,%3}, [%4];"
                 : "=r"(r0), "=r"(r1), "=r"(r2), "=r"(r3) : "r"(saddr));
}

// Dual-tile layer: one ldmatrix feeds 4 MMAs (2 n-tiles x 2 m-tiles).
template<int KS, int SW>
__device__ __forceinline__ void layerH2(uint32_t (&accA)[16][2], uint32_t (&accB)[16][2],
                                        const uint32_t (&aA)[8][4], const uint32_t (&aB)[8][4],
                                        uint32_t wbase, uint32_t rowsel, uint32_t kbit) {
#pragma unroll
    for (int s = 0; s < KS; s++) {
#pragma unroll
        for (int p = 0; p < 8; p++) {
            uint32_t addr = wbase + (((p * 16 + rowsel) * SW) + s * 16 + kbit) * 2;
            uint32_t b0, b1, b2, b3;
            ldmat4(b0, b1, b2, b3, addr);
            mmah(accA[2 * p],     aA[s], b0, b1);
            mmah(accA[2 * p + 1], aA[s], b2, b3);
            mmah(accB[2 * p],     aB[s], b0, b1);
            mmah(accB[2 * p + 1], aB[s], b2, b3);
        }
    }
}

__device__ __forceinline__ void zero_acc(uint32_t (&acc)[16][2]) {
#pragma unroll
    for (int nt = 0; nt < 16; nt++) { acc[nt][0] = 0u; acc[nt][1] = 0u; }
}

__device__ __forceinline__ void bias_silu(uint32_t (&acc)[16][2], const float* __restrict__ bias, int kb0) {
#pragma unroll
    for (int nt = 0; nt < 16; nt++) {
        float2 b = *reinterpret_cast<const float2*>(bias + nt * 8 + kb0);
        float2 f0 = unpackh2(acc[nt][0]);
        float2 f1 = unpackh2(acc[nt][1]);
        acc[nt][0] = packh2(silu_f(f0.x + b.x), silu_f(f0.y + b.y));
        acc[nt][1] = packh2(silu_f(f1.x + b.x), silu_f(f1.y + b.y));
    }
}
__device__ __forceinline__ void to_afrag(const uint32_t (&acc)[16][2], uint32_t (&a)[8][4]) {
#pragma unroll
    for (int s = 0; s < 8; s++) {
        a[s][0] = acc[2*s][0];   a[s][1] = acc[2*s][1];
        a[s][2] = acc[2*s+1][0]; a[s][3] = acc[2*s+1][1];
    }
}

__device__ __forceinline__ void load_ea_frags(const float* __restrict__ edge_attr,
                                              int r0, int r1, int kb0, uint32_t (&a)[8][4]) {
#pragma unroll
    for (int s = 0; s < 2; s++) {
        int kb = kb0 + 16 * s;
        a[s][0] = packh2_f2(*(const float2*)(edge_attr + (size_t)r0 * 32 + kb));
        a[s][1] = packh2_f2(*(const float2*)(edge_attr + (size_t)r1 * 32 + kb));
        a[s][2] = packh2_f2(*(const float2*)(edge_attr + (size_t)r0 * 32 + kb + 8));
        a[s][3] = packh2_f2(*(const float2*)(edge_attr + (size_t)r1 * 32 + kb + 8));
    }
}

#define SW_K32  40
#define SW_K128 136
#define SW_K64  72
#define SW_K16  24
#define EDGE_THREADS 192
#define EDGE_WARPS 6
#define EDGE_GRID 296

// ===================== node precompute via mma (xW, preA, preB) — 1-tile =====================
__global__ void __launch_bounds__(EDGE_THREADS, 3) node_pre_mma_kernel(
    const float* __restrict__ nf, const float* __restrict__ Wnode,
    const float* __restrict__ aW1) {
    extern __shared__ char smch[];
    __half* sWn = (__half*)smch;                // [128][136]
    __half* sWa = sWn + 128 * SW_K128;          // [128][72]
    __half* sWb = sWa + 128 * SW_K64;           // [128][72]

    int t = threadIdx.x;
    for (int i = t; i < 16384; i += EDGE_THREADS) {
        int k = i >> 7, n = i & 127;
        sWn[n * SW_K128 + k] = __float2half(Wnode[i]);
    }
    for (int i = t; i < 8192; i += EDGE_THREADS) {
        int k = i >> 7, n = i & 127;
        sWa[n * SW_K64 + k] = __float2half(aW1[i]);
        sWb[n * SW_K64 + k] = __float2half(aW1[8192 + i]);
    }
    __syncthreads();

    uint32_t bWn = smem_u32(sWn), bWa = smem_u32(sWa), bWb = smem_u32(sWb);
    int lane = t & 31, warp = t >> 5;
    uint32_t rowsel = (uint32_t)(((lane >> 4) << 3) | (lane & 7));
    uint32_t kbit = (uint32_t)(((lane >> 3) & 1) * 8);
    int kb0 = (lane & 3) * 2;

    int gw = blockIdx.x * EDGE_WARPS + warp;
    int nw = gridDim.x * EDGE_WARPS;
    for (int wt = gw; wt < NN / 16; wt += nw) {
        int r0 = wt * 16 + (lane >> 2), r1 = r0 + 8;
        uint32_t a[8][4];
#pragma unroll
        for (int s = 0; s < 8; s++) {
            int kb = 16 * s + kb0;
            a[s][0] = packh2_f2(*(const float2*)(nf + (size_t)r0 * 128 + kb));
            a[s][1] = packh2_f2(*(const float2*)(nf + (size_t)r1 * 128 + kb));
            a[s][2] = packh2_f2(*(const float2*)(nf + (size_t)r0 * 128 + kb + 8));
            a[s][3] = packh2_f2(*(const float2*)(nf + (size_t)r1 * 128 + kb + 8));
        }
        uint32_t acc[16][2];
        zero_acc(acc);
        {   // reuse dual-layer helper with same A twice would waste; plain loop:
#pragma unroll
            for (int s = 0; s < 8; s++)
#pragma unroll
                for (int p = 0; p < 8; p++) {
                    uint32_t addr = bWn + (((p * 16 + rowsel) * SW_K128) + s * 16 + kbit) * 2;
                    uint32_t b0, b1, b2, b3;
                    ldmat4(b0, b1, b2, b3, addr);
                    mmah(acc[2 * p],     a[s], b0, b1);
                    mmah(acc[2 * p + 1], a[s], b2, b3);
                }
        }
#pragma unroll
        for (int nt = 0; nt < 16; nt++) {
            int col = nt * 8 + kb0;
            *(uint32_t*)(g_xW + (size_t)r0 * 128 + col) = acc[nt][0];
            *(uint32_t*)(g_xW + (size_t)r1 * 128 + col) = acc[nt][1];
        }
        zero_acc(acc);
#pragma unroll
        for (int s = 0; s < 4; s++)
#pragma unroll
            for (int p = 0; p < 8; p++) {
                uint32_t addr = bWa + (((p * 16 + rowsel) * SW_K64) + s * 16 + kbit) * 2;
                uint32_t b0, b1, b2, b3;
                ldmat4(b0, b1, b2, b3, addr);
                mmah(acc[2 * p],     a[s], b0, b1);
                mmah(acc[2 * p + 1], a[s], b2, b3);
            }
#pragma unroll
        for (int nt = 0; nt < 16; nt++) {
            int col = nt * 8 + kb0;
            *(uint32_t*)(g_preA + (size_t)r0 * 128 + col) = acc[nt][0];
            *(uint32_t*)(g_preA + (size_t)r1 * 128 + col) = acc[nt][1];
        }
        zero_acc(acc);
#pragma unroll
        for (int s = 0; s < 4; s++)
#pragma unroll
            for (int p = 0; p < 8; p++) {
                uint32_t addr = bWb + (((p * 16 + rowsel) * SW_K64) + s * 16 + kbit) * 2;
                uint32_t b0, b1, b2, b3;
                ldmat4(b0, b1, b2, b3, addr);
                mmah(acc[2 * p],     a[s], b0, b1);
                mmah(acc[2 * p + 1], a[s], b2, b3);
            }
#pragma unroll
        for (int nt = 0; nt < 16; nt++) {
            int col = nt * 8 + kb0;
            *(uint32_t*)(g_preB + (size_t)r0 * 128 + col) = acc[nt][0];
            *(uint32_t*)(g_preB + (size_t)r1 * 128 + col) = acc[nt][1];
        }
    }
}

// ===================== edge_msg (persistent, dual-tile f16 mma) =====================
__global__ void __launch_bounds__(EDGE_THREADS, 2) edge_msg_mma_kernel(
    const float* __restrict__ edge_attr, const float* __restrict__ edge_sh,
    const float* __restrict__ fc1, const float* __restrict__ b1,
    const float* __restrict__ fc2, const float* __restrict__ b2,
    const float* __restrict__ fc3, const float* __restrict__ b3,
    const float* __restrict__ Wsh, const int* __restrict__ ei) {
    extern __shared__ char smch[];
    __half* sFc1 = (__half*)smch;                   // [128][40]
    __half* sFc2 = sFc1 + 128 * SW_K32;             // [128][136]
    __half* sFc3 = sFc2 + 128 * SW_K128;            // [128][136]
    __half* sWsh = sFc3 + 128 * SW_K128;            // [128][24]
    float* sB1 = (float*)(sWsh + 128 * SW_K16);
    float* sB2 = sB1 + 128;
    float* sB3 = sB2 + 128;

    int t = threadIdx.x;
    for (int i = t; i < 4096; i += EDGE_THREADS) {
        int k = i >> 7, n = i & 127;
        sFc1[n * SW_K32 + k] = __float2half(fc1[i]);
    }
    for (int i = t; i < 16384; i += EDGE_THREADS) {
        int k = i >> 7, n = i & 127;
        sFc2[n * SW_K128 + k] = __float2half(fc2[i]);
        sFc3[n * SW_K128 + k] = __float2half(fc3[i]);
    }
    for (int i = t; i < 2048; i += EDGE_THREADS) {
        int k = i >> 7, n = i & 127;
        sWsh[n * SW_K16 + k] = __float2half(Wsh[i]);
    }
    if (t < 128) { sB1[t] = b1[t]; sB2[t] = b2[t]; sB3[t] = b3[t]; }
    __syncthreads();

    uint32_t bFc1 = smem_u32(sFc1), bFc2 = smem_u32(sFc2), bFc3 = smem_u32(sFc3), bWsh = smem_u32(sWsh);
    int lane = t & 31, warp = t >> 5;
    uint32_t rowsel = (uint32_t)(((lane >> 4) << 3) | (lane & 7));
    uint32_t kbit = (uint32_t)(((lane >> 3) & 1) * 8);
    int kb0 = (lane & 3) * 2;

    int gw = blockIdx.x * EDGE_WARPS + warp;
    int nw = gridDim.x * EDGE_WARPS;
    for (int wt = gw; wt < NE / 32; wt += nw) {
        int e0 = wt * 32;
        int rA0 = e0 + (lane >> 2), rA1 = rA0 + 8;
        int rB0 = rA0 + 16,         rB1 = rA0 + 24;
        int srcA0 = ei[rA0], srcA1 = ei[rA1], srcB0 = ei[rB0], srcB1 = ei[rB1];

        uint32_t aA[8][4], aB[8][4];
        load_ea_frags(edge_attr, rA0, rA1, kb0, aA);
        load_ea_frags(edge_attr, rB0, rB1, kb0, aB);
        uint32_t ashA[4], ashB[4];
        ashA[0] = packh2_f2(*(const float2*)(edge_sh + (size_t)rA0 * 16 + kb0));
        ashA[1] = packh2_f2(*(const float2*)(edge_sh + (size_t)rA1 * 16 + kb0));
        ashA[2] = packh2_f2(*(const float2*)(edge_sh + (size_t)rA0 * 16 + kb0 + 8));
        ashA[3] = packh2_f2(*(const float2*)(edge_sh + (size_t)rA1 * 16 + kb0 + 8));
        ashB[0] = packh2_f2(*(const float2*)(edge_sh + (size_t)rB0 * 16 + kb0));
        ashB[1] = packh2_f2(*(const float2*)(edge_sh + (size_t)rB1 * 16 + kb0));
        ashB[2] = packh2_f2(*(const float2*)(edge_sh + (size_t)rB0 * 16 + kb0 + 8));
        ashB[3] = packh2_f2(*(const float2*)(edge_sh + (size_t)rB1 * 16 + kb0 + 8));

        uint32_t accA[16][2], accB[16][2];
        zero_acc(accA); zero_acc(accB);
        layerH2<2, SW_K32>(accA, accB, aA, aB, bFc1, rowsel, kbit);
        bias_silu(accA, sB1, kb0); to_afrag(accA, aA);
        bias_silu(accB, sB1, kb0); to_afrag(accB, aB);
        zero_acc(accA); zero_acc(accB);
        layerH2<8, SW_K128>(accA, accB, aA, aB, bFc2, rowsel, kbit);
        bias_silu(accA, sB2, kb0); to_afrag(accA, aA);
        bias_silu(accB, sB2, kb0); to_afrag(accB, aB);
        zero_acc(accA); zero_acc(accB);
        layerH2<8, SW_K128>(accA, accB, aA, aB, bFc3, rowsel, kbit);  // scale (pre-bias)
        // epilogue: shv mma (shared ldmatrix) + combine, store f16 msg
#pragma unroll
        for (int p = 0; p < 8; p++) {
            uint32_t b0, b1, b2, b3;
            uint32_t addr = bWsh + (((p * 16 + rowsel) * SW_K16) + kbit) * 2;
            ldmat4(b0, b1, b2, b3, addr);
            uint32_t tA0[2] = {0u,0u}, tA1[2] = {0u,0u}, tB0[2] = {0u,0u}, tB1[2] = {0u,0u};
            mmah(tA0, ashA, b0, b1); mmah(tA1, ashA, b2, b3);
            mmah(tB0, ashB, b0, b1); mmah(tB1, ashB, b2, b3);
#pragma unroll
            for (int q = 0; q < 2; q++) {
                int nt = 2 * p + q;
                int col = nt * 8 + kb0;
                float2 bv = *(const float2*)(sB3 + col);
                {   // tile A
                    const uint32_t* tv = q ? tA1 : tA0;
                    float2 sc0 = unpackh2(accA[nt][0]), sc1 = unpackh2(accA[nt][1]);
                    float2 sh0 = unpackh2(tv[0]), sh1 = unpackh2(tv[1]);
                    float2 xw0 = unpackh2(*(const uint32_t*)(g_xW + (size_t)srcA0 * 128 + col));
                    float2 xw1 = unpackh2(*(const uint32_t*)(g_xW + (size_t)srcA1 * 128 + col));
                    *(uint32_t*)(g_msg + (size_t)rA0 * 128 + col) =
                        packh2(silu_f(fmaf(xw0.x, sc0.x + bv.x, sh0.x)),
                               silu_f(fmaf(xw0.y, sc0.y + bv.y, sh0.y)));
                    *(uint32_t*)(g_msg + (size_t)rA1 * 128 + col) =
                        packh2(silu_f(fmaf(xw1.x, sc1.x + bv.x, sh1.x)),
                               silu_f(fmaf(xw1.y, sc1.y + bv.y, sh1.y)));
                }
                {   // tile B
                    const uint32_t* tv = q ? tB1 : tB0;
                    float2 sc0 = unpackh2(accB[nt][0]), sc1 = unpackh2(accB[nt][1]);
                    float2 sh0 = unpackh2(tv[0]), sh1 = unpackh2(tv[1]);
                    float2 xw0 = unpackh2(*(const uint32_t*)(g_xW + (size_t)srcB0 * 128 + col));
                    float2 xw1 = unpackh2(*(const uint32_t*)(g_xW + (size_t)srcB1 * 128 + col));
                    *(uint32_t*)(g_msg + (size_t)rB0 * 128 + col) =
                        packh2(silu_f(fmaf(xw0.x, sc0.x + bv.x, sh0.x)),
                               silu_f(fmaf(xw0.y, sc0.y + bv.y, sh0.y)));
                    *(uint32_t*)(g_msg + (size_t)rB1 * 128 + col) =
                        packh2(silu_f(fmaf(xw1.x, sc1.x + bv.x, sh1.x)),
                               silu_f(fmaf(xw1.y, sc1.y + bv.y, sh1.y)));
                }
            }
        }
    }
}

// ===================== edge_att (persistent, dual-tile f16 mma) =====================
__global__ void __launch_bounds__(EDGE_THREADS, 2) edge_att_mma_kernel(
    const float* __restrict__ edge_attr,
    const float* __restrict__ aW1, const float* __restrict__ ab1,
    const float* __restrict__ aW2, const float* __restrict__ ab2,
    const float* __restrict__ aW3, const float* __restrict__ ab3,
    const int* __restrict__ ei) {
    extern __shared__ char smch[];
    __half* sA1e = (__half*)smch;                   // [128][40]
    __half* sA2  = sA1e + 128 * SW_K32;             // [128][136]
    __half* sA3  = sA2 + 128 * SW_K128;             // [8][136]
    float* sAb1 = (float*)(sA3 + 8 * SW_K128);
    float* sAb2 = sAb1 + 128;
    float* sAb3 = sAb2 + 128;

    int t = threadIdx.x;
    for (int i = t; i < 4096; i += EDGE_THREADS) {
        int k = i >> 7, n = i & 127;
        sA1e[n * SW_K32 + k] = __float2half(aW1[(128 + k) * 128 + n]);
    }
    for (int i = t; i < 16384; i += EDGE_THREADS) {
        int k = i >> 7, n = i & 127;
        sA2[n * SW_K128 + k] = __float2half(aW2[i]);
    }
    for (int i = t; i < 1024; i += EDGE_THREADS) {
        int k = i >> 3, n = i & 7;
        sA3[n * SW_K128 + k] = __float2half(aW3[i]);
    }
    if (t < 128) { sAb1[t] = ab1[t]; sAb2[t] = ab2[t]; }
    if (t < 8) sAb3[t] = ab3[t];
    __syncthreads();

    uint32_t bA1e = smem_u32(sA1e), bA2 = smem_u32(sA2);
    int lane = t & 31, warp = t >> 5;
    uint32_t rowsel = (uint32_t)(((lane >> 4) << 3) | (lane & 7));
    uint32_t kbit = (uint32_t)(((lane >> 3) & 1) * 8);
    int kb0 = (lane & 3) * 2;

    int gw = blockIdx.x * EDGE_WARPS + warp;
    int nw = gridDim.x * EDGE_WARPS;
    for (int wt = gw; wt < NE / 32; wt += nw) {
        int e0 = wt * 32;
        int rA0 = e0 + (lane >> 2), rA1 = rA0 + 8;
        int rB0 = rA0 + 16,         rB1 = rA0 + 24;

        uint32_t aA[8][4], aB[8][4];
        load_ea_frags(edge_attr, rA0, rA1, kb0, aA);
        load_ea_frags(edge_attr, rB0, rB1, kb0, aB);

        uint32_t accA[16][2], accB[16][2];
        zero_acc(accA); zero_acc(accB);
        layerH2<2, SW_K32>(accA, accB, aA, aB, bA1e, rowsel, kbit);
        // epilogue 1: + preA[src] + preB[dst] + ab1, silu (fp32 math)
        {
            int sA0 = ei[rA0], sA1i = ei[rA1], sB0 = ei[rB0], sB1i = ei[rB1];
            int dA0 = ei[NE + rA0], dA1 = ei[NE + rA1], dB0 = ei[NE + rB0], dB1 = ei[NE + rB1];
#pragma unroll
            for (int nt = 0; nt < 16; nt++) {
                int col = nt * 8 + kb0;
                float2 bv = *(const float2*)(sAb1 + col);
                {
                    float2 f0 = unpackh2(accA[nt][0]), f1 = unpackh2(accA[nt][1]);
                    float2 pa0 = unpackh2(*(const uint32_t*)(g_preA + (size_t)sA0 * 128 + col));
                    float2 pb0 = unpackh2(*(const uint32_t*)(g_preB + (size_t)dA0 * 128 + col));
                    float2 pa1 = unpackh2(*(const uint32_t*)(g_preA + (size_t)sA1i * 128 + col));
                    float2 pb1 = unpackh2(*(const uint32_t*)(g_preB + (size_t)dA1 * 128 + col));
                    accA[nt][0] = packh2(silu_f(f0.x + bv.x + pa0.x + pb0.x),
                                         silu_f(f0.y + bv.y + pa0.y + pb0.y));
                    accA[nt][1] = packh2(silu_f(f1.x + bv.x + pa1.x + pb1.x),
                                         silu_f(f1.y + bv.y + pa1.y + pb1.y));
                }
                {
                    float2 f0 = unpackh2(accB[nt][0]), f1 = unpackh2(accB[nt][1]);
                    float2 pa0 = unpackh2(*(const uint32_t*)(g_preA + (size_t)sB0 * 128 + col));
                    float2 pb0 = unpackh2(*(const uint32_t*)(g_preB + (size_t)dB0 * 128 + col));
                    float2 pa1 = unpackh2(*(const uint32_t*)(g_preA + (size_t)sB1i * 128 + col));
                    float2 pb1 = unpackh2(*(const uint32_t*)(g_preB + (size_t)dB1 * 128 + col));
                    accB[nt][0] = packh2(silu_f(f0.x + bv.x + pa0.x + pb0.x),
                                         silu_f(f0.y + bv.y + pa0.y + pb0.y));
                    accB[nt][1] = packh2(silu_f(f1.x + bv.x + pa1.x + pb1.x),
                                         silu_f(f1.y + bv.y + pa1.y + pb1.y));
                }
            }
        }
        to_afrag(accA, aA); to_afrag(accB, aB);
        zero_acc(accA); zero_acc(accB);
        layerH2<8, SW_K128>(accA, accB, aA, aB, bA2, rowsel, kbit);
        bias_silu(accA, sAb2, kb0); to_afrag(accA, aA);
        bias_silu(accB, sAb2, kb0); to_afrag(accB, aB);
        // layer 3: N=8, single n-tile, per tile
        uint32_t cA[2] = {0u, 0u}, cB[2] = {0u, 0u};
#pragma unroll
        for (int s = 0; s < 8; s++) {
            const __half* wp = sA3 + (size_t)(lane >> 2) * SW_K128 + kb0 + 16 * s;
            uint32_t w0 = *(const uint32_t*)wp, w1 = *(const uint32_t*)(wp + 8);
            mmah(cA, aA[s], w0, w1);
            mmah(cB, aB[s], w0, w1);
        }
        float2 b3 = *(const float2*)(sAb3 + kb0);
        float2 oA0 = unpackh2(cA[0]), oA1 = unpackh2(cA[1]);
        float2 oB0 = unpackh2(cB[0]), oB1 = unpackh2(cB[1]);
        *(float2*)(g_a + (size_t)rA0 * 8 + kb0) = make_float2(oA0.x + b3.x, oA0.y + b3.y);
        *(float2*)(g_a + (size_t)rA1 * 8 + kb0) = make_float2(oA1.x + b3.x, oA1.y + b3.y);
        *(float2*)(g_a + (size_t)rB0 * 8 + kb0) = make_float2(oB0.x + b3.x, oB0.y + b3.y);
        *(float2*)(g_a + (size_t)rB1 * 8 + kb0) = make_float2(oB1.x + b3.x, oB1.y + b3.y);
    }
}

// ===================== reductions / scatter / final =====================
__global__ void __launch_bounds__(256) init_kernel() {
    int tid = blockIdx.x * blockDim.x + threadIdx.x;
    if (tid < NHH) { g_maxh[tid] = -3.0e38f; g_sumh[tid] = 0.0f; }
    float4* a4 = reinterpret_cast<float4*>(g_agg);
    int stride = gridDim.x * blockDim.x;
    for (int i = tid; i < NN * 32; i += stride) a4[i] = make_float4(0.f, 0.f, 0.f, 0.f);
}

__global__ void __launch_bounds__(256) redmax_kernel() {
    float m[8];
#pragma unroll
    for (int h = 0; h < 8; h++) m[h] = -3.0e38f;
    int stride = gridDim.x * blockDim.x;
    for (int e = blockIdx.x * blockDim.x + threadIdx.x; e < NE; e += stride) {
        const float4* ap = reinterpret_cast<const float4*>(g_a + (size_t)e * 8);
        float4 a0 = ap[0], a1 = ap[1];
        m[0]=fmaxf(m[0],a0.x); m[1]=fmaxf(m[1],a0.y); m[2]=fmaxf(m[2],a0.z); m[3]=fmaxf(m[3],a0.w);
        m[4]=fmaxf(m[4],a1.x); m[5]=fmaxf(m[5],a1.y); m[6]=fmaxf(m[6],a1.z); m[7]=fmaxf(m[7],a1.w);
    }
#pragma unroll
    for (int off = 16; off >= 1; off >>= 1)
#pragma unroll
        for (int h = 0; h < 8; h++)
            m[h] = fmaxf(m[h], __shfl_xor_sync(0xffffffffu, m[h], off));
    __shared__ float smax[8][8];
    int w = threadIdx.x >> 5, l = threadIdx.x & 31;
    if (l == 0)
        for (int h = 0; h < 8; h++) smax[w][h] = m[h];
    __syncthreads();
    if (threadIdx.x < 8) {
        float mm = -3.0e38f;
        for (int w2 = 0; w2 < 8; w2++) mm = fmaxf(mm, smax[w2][threadIdx.x]);
        atomicMaxF(&g_maxh[threadIdx.x], mm);
    }
}

__global__ void __launch_bounds__(256) redsum_kernel() {
    float mh[8], s[8];
#pragma unroll
    for (int h = 0; h < 8; h++) { mh[h] = g_maxh[h]; s[h] = 0.f; }
    int stride = gridDim.x * blockDim.x;
    for (int e = blockIdx.x * blockDim.x + threadIdx.x; e < NE; e += stride) {
        const float4* ap = reinterpret_cast<const float4*>(g_a + (size_t)e * 8);
        float4 a0 = ap[0], a1 = ap[1];
        s[0]+=__expf(a0.x-mh[0]); s[1]+=__expf(a0.y-mh[1]); s[2]+=__expf(a0.z-mh[2]); s[3]+=__expf(a0.w-mh[3]);
        s[4]+=__expf(a1.x-mh[4]); s[5]+=__expf(a1.y-mh[5]); s[6]+=__expf(a1.z-mh[6]); s[7]+=__expf(a1.w-mh[7]);
    }
#pragma unroll
    for (int off = 16; off >= 1; off >>= 1)
#pragma unroll
        for (int h = 0; h < 8; h++)
            s[h] += __shfl_xor_sync(0xffffffffu, s[h], off);
    __shared__ float ssum[8][8];
    int w = threadIdx.x >> 5, l = threadIdx.x & 31;
    if (l == 0)
        for (int h = 0; h < 8; h++) ssum[w][h] = s[h];
    __syncthreads();
    if (threadIdx.x < 8) {
        float tot = 0.f;
        for (int w2 = 0; w2 < 8; w2++) tot += ssum[w2][threadIdx.x];
        atomicAdd(&g_sumh[threadIdx.x], tot);
    }
}

__global__ void __launch_bounds__(256) scatter_kernel(const int* __restrict__ ei) {
    float mh[8], inv[8];
#pragma unroll
    for (int h = 0; h < 8; h++) { mh[h] = g_maxh[h]; inv[h] = __frcp_rn(g_sumh[h]); }
    int lane = threadIdx.x & 31;
    int warp = (blockIdx.x * blockDim.x + threadIdx.x) >> 5;
    int nwarps = (gridDim.x * blockDim.x) >> 5;
    for (int e = warp; e < NE; e += nwarps) {
        const float4* ap = reinterpret_cast<const float4*>(g_a + (size_t)e * 8);
        float4 a0 = ap[0], a1 = ap[1];
        float am = __expf(a0.x-mh[0])*inv[0] + __expf(a0.y-mh[1])*inv[1]
                 + __expf(a0.z-mh[2])*inv[2] + __expf(a0.w-mh[3])*inv[3]
                 + __expf(a1.x-mh[4])*inv[4] + __expf(a1.y-mh[5])*inv[5]
                 + __expf(a1.z-mh[6])*inv[6] + __expf(a1.w-mh[7])*inv[7];
        am *= 0.125f;
        int d = ei[NE + e];
        uint2 mv = *reinterpret_cast<const uint2*>(g_msg + (size_t)e * 128 + 4 * lane);
        float2 f0 = unpackh2(mv.x), f1 = unpackh2(mv.y);
        float* dst = g_agg + (size_t)d * 128 + 4 * lane;
        asm volatile("red.global.add.v4.f32 [%0], {%1, %2, %3, %4};"
                     :: "l"(dst), "f"(f0.x*am), "f"(f0.y*am), "f"(f1.x*am), "f"(f1.y*am)
                     : "memory");
    }
}

__global__ void __launch_bounds__(256) final_kernel(const float* __restrict__ nf,
                                                    const float* __restrict__ Wout,
                                                    float* __restrict__ out) {
    extern __shared__ float sm[];
    float* sW = sm;
    float* sRows = sm + 16384;
    int t = threadIdx.x;
    for (int i = t; i < 16384; i += 256) sW[i] = Wout[i];
    int row0 = blockIdx.x * 32;
    for (int i = t; i < 4096; i += 256) {
        int r = row0 + (i >> 7);
        sRows[i] = (r < NN) ? g_agg[(size_t)r * 128 + (i & 127)] : 0.f;
    }
    __syncthreads();
    int warp = t >> 5, lane = t & 31;
    for (int rr = warp; rr < 32; rr += 8) {
        int r = row0 + rr;
        if (r >= NN) continue;
        const float* arow = sRows + rr * 128;
        float4 acc = make_float4(0.f,0.f,0.f,0.f);
#pragma unroll 4
        for (int k = 0; k < 128; k++) {
            float a = arow[k];
            float4 w = reinterpret_cast<const float4*>(sW + k * 128)[lane];
            acc.x = fmaf(a, w.x, acc.x); acc.y = fmaf(a, w.y, acc.y);
            acc.z = fmaf(a, w.z, acc.z); acc.w = fmaf(a, w.w, acc.w);
        }
        float4 x = reinterpret_cast<const float4*>(nf + (size_t)r * 128)[lane];
        float4 o = make_float4(x.x+acc.x, x.y+acc.y, x.z+acc.z, x.w+acc.w);
        float sum = o.x + o.y + o.z + o.w;
        float sq  = o.x*o.x + o.y*o.y + o.z*o.z + o.w*o.w;
#pragma unroll
        for (int off = 16; off >= 1; off >>= 1) {
            sum += __shfl_xor_sync(0xffffffffu, sum, off);
            sq  += __shfl_xor_sync(0xffffffffu, sq, off);
        }
        float mu = sum * (1.0f / 128.0f);
        float var = sq * (1.0f / 128.0f) - mu * mu;
        float rs = rsqrtf(var + 1e-5f);
        float4 res = make_float4((o.x-mu)*rs, (o.y-mu)*rs, (o.z-mu)*rs, (o.w-mu)*rs);
        reinterpret_cast<float4*>(out + (size_t)r * 128)[lane] = res;
    }
}

extern "C" void kernel_launch(void* const* d_in, const int* in_sizes, int n_in,
                              void* d_out, int out_size) {
    const float* nf    = (const float*)d_in[0];
    const float* eattr = (const float*)d_in[1];
    const float* esh   = (const float*)d_in[2];
    const float* Wnode = (const float*)d_in[3];
    const float* fc1   = (const float*)d_in[4];
    const float* b1    = (const float*)d_in[5];
    const float* fc2   = (const float*)d_in[6];
    const float* b2    = (const float*)d_in[7];
    const float* fc3   = (const float*)d_in[8];
    const float* b3    = (const float*)d_in[9];
    const float* Wsh   = (const float*)d_in[10];
    const float* aW1   = (const float*)d_in[11];
    const float* ab1   = (const float*)d_in[12];
    const float* aW2   = (const float*)d_in[13];
    const float* ab2   = (const float*)d_in[14];
    const float* aW3   = (const float*)d_in[15];
    const float* ab3   = (const float*)d_in[16];
    const float* Wout  = (const float*)d_in[17];
    const int*   ei    = (const int*)d_in[18];
    float* out = (float*)d_out;

    const int SM_NODE  = (128*SW_K128 + 2*128*SW_K64) * 2;
    const int SM_MSG   = (128*SW_K32 + 2*128*SW_K128 + 128*SW_K16) * 2 + 3 * 128 * 4 + 64;
    const int SM_ATT   = (128*SW_K32 + 128*SW_K128 + 8*SW_K128) * 2 + (128+128+8) * 4 + 64;
    const int SM_FINAL = (16384 + 4096) * 4;
    cudaFuncSetAttribute(node_pre_mma_kernel, cudaFuncAttributeMaxDynamicSharedMemorySize, SM_NODE);
    cudaFuncSetAttribute(edge_msg_mma_kernel, cudaFuncAttributeMaxDynamicSharedMemorySize, SM_MSG);
    cudaFuncSetAttribute(edge_att_mma_kernel, cudaFuncAttributeMaxDynamicSharedMemorySize, SM_ATT);
    cudaFuncSetAttribute(final_kernel,        cudaFuncAttributeMaxDynamicSharedMemorySize, SM_FINAL);

    init_kernel<<<4096, 256>>>();
    node_pre_mma_kernel<<<444, EDGE_THREADS, SM_NODE>>>(nf, Wnode, aW1);
    edge_msg_mma_kernel<<<EDGE_GRID, EDGE_THREADS, SM_MSG>>>(eattr, esh, fc1, b1, fc2, b2, fc3, b3, Wsh, ei);
    edge_att_mma_kernel<<<EDGE_GRID, EDGE_THREADS, SM_ATT>>>(eattr, aW1, ab1, aW2, ab2, aW3, ab3, ei);
    redmax_kernel<<<512, 256>>>();
    redsum_kernel<<<512, 256>>>();
    scatter_kernel<<<2048, 256>>>(ei);
    final_kernel<<<(NN + 31) / 32, 256, SM_FINAL>>>(nf, Wout, out);
}

// round 10
// speedup vs baseline: 1.0903x; 1.0903x over previous
#include <cuda_runtime.h>
#include <cuda_fp16.h>
#include <cstdint>
#include <cstddef>

#define NN 50000
#define NE 800000
#define NHH 8

__device__ __align__(16) __half g_xW  [(size_t)NN * 128];
__device__ __align__(16) __half g_preA[(size_t)NN * 128];
__device__ __align__(16) __half g_preB[(size_t)NN * 128];
__device__ __align__(16) __half g_msg [(size_t)NE * 128];
__device__ __align__(16) float  g_a   [(size_t)NE * 8];
__device__ __align__(16) float  g_agg [(size_t)NN * 128];
__device__ float g_maxh[NHH];
__device__ float g_sumh[NHH];

__device__ __forceinline__ float silu_f(float x) { return __fdividef(x, 1.0f + __expf(-x)); }

__device__ __forceinline__ void atomicMaxF(float* addr, float val) {
    int old = __float_as_int(*addr);
    while (__int_as_float(old) < val) {
        int assumed = old;
        old = atomicCAS((int*)addr, assumed, __float_as_int(val));
        if (old == assumed) break;
    }
}

__device__ __forceinline__ uint32_t smem_u32(const void* p) {
    uint32_t a;
    asm("{ .reg .u64 t; cvta.to.shared.u64 t, %1; cvt.u32.u64 %0, t; }" : "=r"(a) : "l"(p));
    return a;
}

__device__ __forceinline__ uint32_t packh2(float a, float b) {
    __half2 h = __floats2half2_rn(a, b);
    return *reinterpret_cast<uint32_t*>(&h);
}
__device__ __forceinline__ float2 unpackh2(uint32_t u) {
    return __half22float2(*reinterpret_cast<__half2*>(&u));
}
__device__ __forceinline__ uint32_t packh2_f2(float2 v) { return packh2(v.x, v.y); }

// m16n8k16 row.col f16 x f16 -> f16 accum
__device__ __forceinline__ void mmah(uint32_t* c, const uint32_t* a, uint32_t b0, uint32_t b1) {
    asm volatile("mma.sync.aligned.m16n8k16.row.col.f16.f16.f16.f16 "
                 "{%0,%1}, {%2,%3,%4,%5}, {%6,%7}, {%0,%1};"
                 : "+r"(c[0]), "+r"(c[1])
                 : "r"(a[0]), "r"(a[1]), "r"(a[2]), "r"(a[3]), "r"(b0), "r"(b1));
}

__device__ __forceinline__ void ldmat4(uint32_t& r0, uint32_t& r1, uint32_t& r2, uint32_t& r3,
                                       uint32_t saddr) {
    asm volatile("ldmatrix.sync.aligned.m8n8.x4.shared.b16 {%0,%1,%2,%3}, [%4];"
                 : "=r"(r0), "=r"(r1), "=r"(r2), "=r"(r3) : "r"(saddr));
}

template<int KS, int SW>
__device__ __forceinline__ void layerH(uint32_t (&acc)[16][2], const uint32_t (&a)[8][4],
                                       uint32_t wbase, uint32_t rowsel, uint32_t kbit) {
#pragma unroll
    for (int s = 0; s < KS; s++) {
#pragma unroll
        for (int p = 0; p < 8; p++) {
            uint32_t addr = wbase + (((p * 16 + rowsel) * SW) + s * 16 + kbit) * 2;
            uint32_t b0, b1, b2, b3;
            ldmat4(b0, b1, b2, b3, addr);
            mmah(acc[2 * p],     a[s], b0, b1);
            mmah(acc[2 * p + 1], a[s], b2, b3);
        }
    }
}

__device__ __forceinline__ void zero_acc(uint32_t (&acc)[16][2]) {
#pragma unroll
    for (int nt = 0; nt < 16; nt++) { acc[nt][0] = 0u; acc[nt][1] = 0u; }
}

__device__ __forceinline__ void bias_silu(uint32_t (&acc)[16][2], const float* __restrict__ bias, int kb0) {
#pragma unroll
    for (int nt = 0; nt < 16; nt++) {
        float2 b = *reinterpret_cast<const float2*>(bias + nt * 8 + kb0);
        float2 f0 = unpackh2(acc[nt][0]);
        float2 f1 = unpackh2(acc[nt][1]);
        acc[nt][0] = packh2(silu_f(f0.x + b.x), silu_f(f0.y + b.y));
        acc[nt][1] = packh2(silu_f(f1.x + b.x), silu_f(f1.y + b.y));
    }
}
__device__ __forceinline__ void to_afrag(const uint32_t (&acc)[16][2], uint32_t (&a)[8][4]) {
#pragma unroll
    for (int s = 0; s < 8; s++) {
        a[s][0] = acc[2*s][0];   a[s][1] = acc[2*s][1];
        a[s][2] = acc[2*s+1][0]; a[s][3] = acc[2*s+1][1];
    }
}

#define SW_K32  40
#define SW_K128 136
#define SW_K64  72
#define SW_K16  24
#define ATT_THREADS 192
#define ATT_WARPS 6
#define ATT_GRID 444
#define MSG_THREADS 256
#define MSG_WARPS 8
#define MSG_GRID 296

// ===================== node precompute via mma (xW, preA, preB) =====================
__global__ void __launch_bounds__(ATT_THREADS, 3) node_pre_mma_kernel(
    const float* __restrict__ nf, const float* __restrict__ Wnode,
    const float* __restrict__ aW1) {
    extern __shared__ char smch[];
    __half* sWn = (__half*)smch;                // [128][136]
    __half* sWa = sWn + 128 * SW_K128;          // [128][72]
    __half* sWb = sWa + 128 * SW_K64;           // [128][72]

    int t = threadIdx.x;
    for (int i = t; i < 16384; i += ATT_THREADS) {
        int k = i >> 7, n = i & 127;
        sWn[n * SW_K128 + k] = __float2half(Wnode[i]);
    }
    for (int i = t; i < 8192; i += ATT_THREADS) {
        int k = i >> 7, n = i & 127;
        sWa[n * SW_K64 + k] = __float2half(aW1[i]);
        sWb[n * SW_K64 + k] = __float2half(aW1[8192 + i]);
    }
    __syncthreads();

    uint32_t bWn = smem_u32(sWn), bWa = smem_u32(sWa), bWb = smem_u32(sWb);
    int lane = t & 31, warp = t >> 5;
    uint32_t rowsel = (uint32_t)(((lane >> 4) << 3) | (lane & 7));
    uint32_t kbit = (uint32_t)(((lane >> 3) & 1) * 8);
    int kb0 = (lane & 3) * 2;

    int gw = blockIdx.x * ATT_WARPS + warp;
    int nw = gridDim.x * ATT_WARPS;
    for (int wt = gw; wt < NN / 16; wt += nw) {
        int r0 = wt * 16 + (lane >> 2), r1 = r0 + 8;
        uint32_t a[8][4];
#pragma unroll
        for (int s = 0; s < 8; s++) {
            int kb = 16 * s + kb0;
            a[s][0] = packh2_f2(*(const float2*)(nf + (size_t)r0 * 128 + kb));
            a[s][1] = packh2_f2(*(const float2*)(nf + (size_t)r1 * 128 + kb));
            a[s][2] = packh2_f2(*(const float2*)(nf + (size_t)r0 * 128 + kb + 8));
            a[s][3] = packh2_f2(*(const float2*)(nf + (size_t)r1 * 128 + kb + 8));
        }
        uint32_t acc[16][2];
        zero_acc(acc);
        layerH<8, SW_K128>(acc, a, bWn, rowsel, kbit);
#pragma unroll
        for (int nt = 0; nt < 16; nt++) {
            int col = nt * 8 + kb0;
            *(uint32_t*)(g_xW + (size_t)r0 * 128 + col) = acc[nt][0];
            *(uint32_t*)(g_xW + (size_t)r1 * 128 + col) = acc[nt][1];
        }
        zero_acc(acc);
        layerH<4, SW_K64>(acc, a, bWa, rowsel, kbit);
#pragma unroll
        for (int nt = 0; nt < 16; nt++) {
            int col = nt * 8 + kb0;
            *(uint32_t*)(g_preA + (size_t)r0 * 128 + col) = acc[nt][0];
            *(uint32_t*)(g_preA + (size_t)r1 * 128 + col) = acc[nt][1];
        }
        zero_acc(acc);
        layerH<4, SW_K64>(acc, a, bWb, rowsel, kbit);
#pragma unroll
        for (int nt = 0; nt < 16; nt++) {
            int col = nt * 8 + kb0;
            *(uint32_t*)(g_preB + (size_t)r0 * 128 + col) = acc[nt][0];
            *(uint32_t*)(g_preB + (size_t)r1 * 128 + col) = acc[nt][1];
        }
    }
}

// ===================== edge_msg (persistent, f16 mma, 256 threads) =====================
__global__ void __launch_bounds__(MSG_THREADS, 2) edge_msg_mma_kernel(
    const float* __restrict__ edge_attr, const float* __restrict__ edge_sh,
    const float* __restrict__ fc1, const float* __restrict__ b1,
    const float* __restrict__ fc2, const float* __restrict__ b2,
    const float* __restrict__ fc3, const float* __restrict__ b3,
    const float* __restrict__ Wsh, const int* __restrict__ ei) {
    extern __shared__ char smch[];
    __half* sFc1 = (__half*)smch;                   // [128][40]
    __half* sFc2 = sFc1 + 128 * SW_K32;             // [128][136]
    __half* sFc3 = sFc2 + 128 * SW_K128;            // [128][136]
    __half* sWsh = sFc3 + 128 * SW_K128;            // [128][24]
    float* sB1 = (float*)(sWsh + 128 * SW_K16);
    float* sB2 = sB1 + 128;
    float* sB3 = sB2 + 128;

    int t = threadIdx.x;
    for (int i = t; i < 4096; i += MSG_THREADS) {
        int k = i >> 7, n = i & 127;
        sFc1[n * SW_K32 + k] = __float2half(fc1[i]);
    }
    for (int i = t; i < 16384; i += MSG_THREADS) {
        int k = i >> 7, n = i & 127;
        sFc2[n * SW_K128 + k] = __float2half(fc2[i]);
        sFc3[n * SW_K128 + k] = __float2half(fc3[i]);
    }
    for (int i = t; i < 2048; i += MSG_THREADS) {
        int k = i >> 7, n = i & 127;
        sWsh[n * SW_K16 + k] = __float2half(Wsh[i]);
    }
    if (t < 128) { sB1[t] = b1[t]; sB2[t] = b2[t]; sB3[t] = b3[t]; }
    __syncthreads();

    uint32_t bFc1 = smem_u32(sFc1), bFc2 = smem_u32(sFc2), bFc3 = smem_u32(sFc3), bWsh = smem_u32(sWsh);
    int lane = t & 31, warp = t >> 5;
    uint32_t rowsel = (uint32_t)(((lane >> 4) << 3) | (lane & 7));
    uint32_t kbit = (uint32_t)(((lane >> 3) & 1) * 8);
    int kb0 = (lane & 3) * 2;

    int gw = blockIdx.x * MSG_WARPS + warp;
    int nw = gridDim.x * MSG_WARPS;
    for (int wt = gw; wt < NE / 16; wt += nw) {
        int r0 = wt * 16 + (lane >> 2), r1 = r0 + 8;
        int src0 = ei[r0], src1 = ei[r1];

        uint32_t a[8][4];
#pragma unroll
        for (int s = 0; s < 2; s++) {
            int kb = kb0 + 16 * s;
            a[s][0] = packh2_f2(*(const float2*)(edge_attr + (size_t)r0 * 32 + kb));
            a[s][1] = packh2_f2(*(const float2*)(edge_attr + (size_t)r1 * 32 + kb));
            a[s][2] = packh2_f2(*(const float2*)(edge_attr + (size_t)r0 * 32 + kb + 8));
            a[s][3] = packh2_f2(*(const float2*)(edge_attr + (size_t)r1 * 32 + kb + 8));
        }
        uint32_t ash[4];
        ash[0] = packh2_f2(*(const float2*)(edge_sh + (size_t)r0 * 16 + kb0));
        ash[1] = packh2_f2(*(const float2*)(edge_sh + (size_t)r1 * 16 + kb0));
        ash[2] = packh2_f2(*(const float2*)(edge_sh + (size_t)r0 * 16 + kb0 + 8));
        ash[3] = packh2_f2(*(const float2*)(edge_sh + (size_t)r1 * 16 + kb0 + 8));

        uint32_t acc[16][2];
        zero_acc(acc);
        layerH<2, SW_K32>(acc, a, bFc1, rowsel, kbit);
        bias_silu(acc, sB1, kb0); to_afrag(acc, a);
        zero_acc(acc);
        layerH<8, SW_K128>(acc, a, bFc2, rowsel, kbit);
        bias_silu(acc, sB2, kb0); to_afrag(acc, a);
        zero_acc(acc);
        layerH<8, SW_K128>(acc, a, bFc3, rowsel, kbit);   // scale (pre-bias)
#pragma unroll
        for (int p = 0; p < 8; p++) {
            uint32_t b0, b1, b2, b3;
            uint32_t addr = bWsh + (((p * 16 + rowsel) * SW_K16) + kbit) * 2;
            ldmat4(b0, b1, b2, b3, addr);
            uint32_t t0[2] = {0u, 0u}, t1[2] = {0u, 0u};
            mmah(t0, ash, b0, b1);
            mmah(t1, ash, b2, b3);
#pragma unroll
            for (int q = 0; q < 2; q++) {
                int nt = 2 * p + q;
                const uint32_t* tv = q ? t1 : t0;
                int col = nt * 8 + kb0;
                float2 bv = *(const float2*)(sB3 + col);
                float2 sc0 = unpackh2(acc[nt][0]), sc1 = unpackh2(acc[nt][1]);
                float2 sh0 = unpackh2(tv[0]), sh1 = unpackh2(tv[1]);
                float2 xw0 = unpackh2(*(const uint32_t*)(g_xW + (size_t)src0 * 128 + col));
                float2 xw1 = unpackh2(*(const uint32_t*)(g_xW + (size_t)src1 * 128 + col));
                *(uint32_t*)(g_msg + (size_t)r0 * 128 + col) =
                    packh2(silu_f(fmaf(xw0.x, sc0.x + bv.x, sh0.x)),
                           silu_f(fmaf(xw0.y, sc0.y + bv.y, sh0.y)));
                *(uint32_t*)(g_msg + (size_t)r1 * 128 + col) =
                    packh2(silu_f(fmaf(xw1.x, sc1.x + bv.x, sh1.x)),
                           silu_f(fmaf(xw1.y, sc1.y + bv.y, sh1.y)));
            }
        }
    }
}

// ===================== edge_att (persistent, f16 mma, 3 CTAs/SM, fused head-max) =====================
__global__ void __launch_bounds__(ATT_THREADS, 3) edge_att_mma_kernel(
    const float* __restrict__ edge_attr,
    const float* __restrict__ aW1, const float* __restrict__ ab1,
    const float* __restrict__ aW2, const float* __restrict__ ab2,
    const float* __restrict__ aW3, const float* __restrict__ ab3,
    const int* __restrict__ ei) {
    extern __shared__ char smch[];
    __half* sA1e = (__half*)smch;                   // [128][40]
    __half* sA2  = sA1e + 128 * SW_K32;             // [128][136]
    __half* sA3  = sA2 + 128 * SW_K128;             // [8][136]
    float* sAb1 = (float*)(sA3 + 8 * SW_K128);
    float* sAb2 = sAb1 + 128;
    float* sAb3 = sAb2 + 128;
    __shared__ float sBMax[ATT_WARPS][8];

    int t = threadIdx.x;
    for (int i = t; i < 4096; i += ATT_THREADS) {
        int k = i >> 7, n = i & 127;
        sA1e[n * SW_K32 + k] = __float2half(aW1[(128 + k) * 128 + n]);
    }
    for (int i = t; i < 16384; i += ATT_THREADS) {
        int k = i >> 7, n = i & 127;
        sA2[n * SW_K128 + k] = __float2half(aW2[i]);
    }
    for (int i = t; i < 1024; i += ATT_THREADS) {
        int k = i >> 3, n = i & 7;
        sA3[n * SW_K128 + k] = __float2half(aW3[i]);
    }
    if (t < 128) { sAb1[t] = ab1[t]; sAb2[t] = ab2[t]; }
    if (t < 8) sAb3[t] = ab3[t];
    __syncthreads();

    uint32_t bA1e = smem_u32(sA1e), bA2 = smem_u32(sA2);
    int lane = t & 31, warp = t >> 5;
    uint32_t rowsel = (uint32_t)(((lane >> 4) << 3) | (lane & 7));
    uint32_t kbit = (uint32_t)(((lane >> 3) & 1) * 8);
    int kb0 = (lane & 3) * 2;

    float mxA = -3.0e38f, mxB = -3.0e38f;   // running max for heads kb0, kb0+1

    int gw = blockIdx.x * ATT_WARPS + warp;
    int nw = gridDim.x * ATT_WARPS;
    for (int wt = gw; wt < NE / 16; wt += nw) {
        int r0 = wt * 16 + (lane >> 2), r1 = r0 + 8;
        int src0 = ei[r0], src1 = ei[r1];
        int dst0 = ei[NE + r0], dst1 = ei[NE + r1];

        uint32_t a[8][4];
#pragma unroll
        for (int s = 0; s < 2; s++) {
            int kb = kb0 + 16 * s;
            a[s][0] = packh2_f2(*(const float2*)(edge_attr + (size_t)r0 * 32 + kb));
            a[s][1] = packh2_f2(*(const float2*)(edge_attr + (size_t)r1 * 32 + kb));
            a[s][2] = packh2_f2(*(const float2*)(edge_attr + (size_t)r0 * 32 + kb + 8));
            a[s][3] = packh2_f2(*(const float2*)(edge_attr + (size_t)r1 * 32 + kb + 8));
        }
        uint32_t acc[16][2];
        zero_acc(acc);
        layerH<2, SW_K32>(acc, a, bA1e, rowsel, kbit);
#pragma unroll
        for (int nt = 0; nt < 16; nt++) {
            int col = nt * 8 + kb0;
            float2 bv = *(const float2*)(sAb1 + col);
            float2 f0 = unpackh2(acc[nt][0]);
            float2 f1 = unpackh2(acc[nt][1]);
            float2 pa0 = unpackh2(*(const uint32_t*)(g_preA + (size_t)src0 * 128 + col));
            float2 pb0 = unpackh2(*(const uint32_t*)(g_preB + (size_t)dst0 * 128 + col));
            float2 pa1 = unpackh2(*(const uint32_t*)(g_preA + (size_t)src1 * 128 + col));
            float2 pb1 = unpackh2(*(const uint32_t*)(g_preB + (size_t)dst1 * 128 + col));
            acc[nt][0] = packh2(silu_f(f0.x + bv.x + pa0.x + pb0.x),
                                silu_f(f0.y + bv.y + pa0.y + pb0.y));
            acc[nt][1] = packh2(silu_f(f1.x + bv.x + pa1.x + pb1.x),
                                silu_f(f1.y + bv.y + pa1.y + pb1.y));
        }
        uint32_t a2[8][4];
        to_afrag(acc, a2);
        zero_acc(acc);
        layerH<8, SW_K128>(acc, a2, bA2, rowsel, kbit);
        bias_silu(acc, sAb2, kb0); to_afrag(acc, a2);
        uint32_t c3[2] = {0u, 0u};
#pragma unroll
        for (int s = 0; s < 8; s++) {
            const __half* wp = sA3 + (size_t)(lane >> 2) * SW_K128 + kb0 + 16 * s;
            mmah(c3, a2[s], *(const uint32_t*)wp, *(const uint32_t*)(wp + 8));
        }
        float2 b3 = *(const float2*)(sAb3 + kb0);
        float2 o0 = unpackh2(c3[0]), o1 = unpackh2(c3[1]);
        o0.x += b3.x; o0.y += b3.y; o1.x += b3.x; o1.y += b3.y;
        mxA = fmaxf(mxA, fmaxf(o0.x, o1.x));
        mxB = fmaxf(mxB, fmaxf(o0.y, o1.y));
        *(float2*)(g_a + (size_t)r0 * 8 + kb0) = o0;
        *(float2*)(g_a + (size_t)r1 * 8 + kb0) = o1;
    }
    // block-level head-max reduction -> g_maxh (replaces redmax kernel)
#pragma unroll
    for (int off = 4; off < 32; off <<= 1) {
        mxA = fmaxf(mxA, __shfl_xor_sync(0xffffffffu, mxA, off));
        mxB = fmaxf(mxB, __shfl_xor_sync(0xffffffffu, mxB, off));
    }
    if (lane < 4) { sBMax[warp][2 * lane] = mxA; sBMax[warp][2 * lane + 1] = mxB; }
    __syncthreads();
    if (t < 8) {
        float m = -3.0e38f;
        for (int w = 0; w < ATT_WARPS; w++) m = fmaxf(m, sBMax[w][t]);
        atomicMaxF(&g_maxh[t], m);
    }
}

// ===================== reductions / scatter / final =====================
__global__ void __launch_bounds__(256) init_kernel() {
    int tid = blockIdx.x * blockDim.x + threadIdx.x;
    if (tid < NHH) { g_maxh[tid] = -3.0e38f; g_sumh[tid] = 0.0f; }
    float4* a4 = reinterpret_cast<float4*>(g_agg);
    int stride = gridDim.x * blockDim.x;
    for (int i = tid; i < NN * 32; i += stride) a4[i] = make_float4(0.f, 0.f, 0.f, 0.f);
}

__global__ void __launch_bounds__(256) redsum_kernel() {
    float mh[8], s[8];
#pragma unroll
    for (int h = 0; h < 8; h++) { mh[h] = g_maxh[h]; s[h] = 0.f; }
    int stride = gridDim.x * blockDim.x;
    for (int e = blockIdx.x * blockDim.x + threadIdx.x; e < NE; e += stride) {
        const float4* ap = reinterpret_cast<const float4*>(g_a + (size_t)e * 8);
        float4 a0 = ap[0], a1 = ap[1];
        s[0]+=__expf(a0.x-mh[0]); s[1]+=__expf(a0.y-mh[1]); s[2]+=__expf(a0.z-mh[2]); s[3]+=__expf(a0.w-mh[3]);
        s[4]+=__expf(a1.x-mh[4]); s[5]+=__expf(a1.y-mh[5]); s[6]+=__expf(a1.z-mh[6]); s[7]+=__expf(a1.w-mh[7]);
    }
#pragma unroll
    for (int off = 16; off >= 1; off >>= 1)
#pragma unroll
        for (int h = 0; h < 8; h++)
            s[h] += __shfl_xor_sync(0xffffffffu, s[h], off);
    __shared__ float ssum[8][8];
    int w = threadIdx.x >> 5, l = threadIdx.x & 31;
    if (l == 0)
        for (int h = 0; h < 8; h++) ssum[w][h] = s[h];
    __syncthreads();
    if (threadIdx.x < 8) {
        float tot = 0.f;
        for (int w2 = 0; w2 < 8; w2++) tot += ssum[w2][threadIdx.x];
        atomicAdd(&g_sumh[threadIdx.x], tot);
    }
}

__global__ void __launch_bounds__(256) scatter_kernel(const int* __restrict__ ei) {
    float mh[8], inv[8];
#pragma unroll
    for (int h = 0; h < 8; h++) { mh[h] = g_maxh[h]; inv[h] = __frcp_rn(g_sumh[h]); }
    int lane = threadIdx.x & 31;
    int warp = (blockIdx.x * blockDim.x + threadIdx.x) >> 5;
    int nwarps = (gridDim.x * blockDim.x) >> 5;
    for (int e = warp; e < NE; e += nwarps) {
        const float4* ap = reinterpret_cast<const float4*>(g_a + (size_t)e * 8);
        float4 a0 = ap[0], a1 = ap[1];
        float am = __expf(a0.x-mh[0])*inv[0] + __expf(a0.y-mh[1])*inv[1]
                 + __expf(a0.z-mh[2])*inv[2] + __expf(a0.w-mh[3])*inv[3]
                 + __expf(a1.x-mh[4])*inv[4] + __expf(a1.y-mh[5])*inv[5]
                 + __expf(a1.z-mh[6])*inv[6] + __expf(a1.w-mh[7])*inv[7];
        am *= 0.125f;
        int d = ei[NE + e];
        uint2 mv = *reinterpret_cast<const uint2*>(g_msg + (size_t)e * 128 + 4 * lane);
        float2 f0 = unpackh2(mv.x), f1 = unpackh2(mv.y);
        float* dst = g_agg + (size_t)d * 128 + 4 * lane;
        asm volatile("red.global.add.v4.f32 [%0], {%1, %2, %3, %4};"
                     :: "l"(dst), "f"(f0.x*am), "f"(f0.y*am), "f"(f1.x*am), "f"(f1.y*am)
                     : "memory");
    }
}

__global__ void __launch_bounds__(256) final_kernel(const float* __restrict__ nf,
                                                    const float* __restrict__ Wout,
                                                    float* __restrict__ out) {
    extern __shared__ float sm[];
    float* sW = sm;
    float* sRows = sm + 16384;
    int t = threadIdx.x;
    for (int i = t; i < 16384; i += 256) sW[i] = Wout[i];
    int row0 = blockIdx.x * 32;
    for (int i = t; i < 4096; i += 256) {
        int r = row0 + (i >> 7);
        sRows[i] = (r < NN) ? g_agg[(size_t)r * 128 + (i & 127)] : 0.f;
    }
    __syncthreads();
    int warp = t >> 5, lane = t & 31;
    for (int rr = warp; rr < 32; rr += 8) {
        int r = row0 + rr;
        if (r >= NN) continue;
        const float* arow = sRows + rr * 128;
        float4 acc = make_float4(0.f,0.f,0.f,0.f);
#pragma unroll 4
        for (int k = 0; k < 128; k++) {
            float a = arow[k];
            float4 w = reinterpret_cast<const float4*>(sW + k * 128)[lane];
            acc.x = fmaf(a, w.x, acc.x); acc.y = fmaf(a, w.y, acc.y);
            acc.z = fmaf(a, w.z, acc.z); acc.w = fmaf(a, w.w, acc.w);
        }
        float4 x = reinterpret_cast<const float4*>(nf + (size_t)r * 128)[lane];
        float4 o = make_float4(x.x+acc.x, x.y+acc.y, x.z+acc.z, x.w+acc.w);
        float sum = o.x + o.y + o.z + o.w;
        float sq  = o.x*o.x + o.y*o.y + o.z*o.z + o.w*o.w;
#pragma unroll
        for (int off = 16; off >= 1; off >>= 1) {
            sum += __shfl_xor_sync(0xffffffffu, sum, off);
            sq  += __shfl_xor_sync(0xffffffffu, sq, off);
        }
        float mu = sum * (1.0f / 128.0f);
        float var = sq * (1.0f / 128.0f) - mu * mu;
        float rs = rsqrtf(var + 1e-5f);
        float4 res = make_float4((o.x-mu)*rs, (o.y-mu)*rs, (o.z-mu)*rs, (o.w-mu)*rs);
        reinterpret_cast<float4*>(out + (size_t)r * 128)[lane] = res;
    }
}

extern "C" void kernel_launch(void* const* d_in, const int* in_sizes, int n_in,
                              void* d_out, int out_size) {
    const float* nf    = (const float*)d_in[0];
    const float* eattr = (const float*)d_in[1];
    const float* esh   = (const float*)d_in[2];
    const float* Wnode = (const float*)d_in[3];
    const float* fc1   = (const float*)d_in[4];
    const float* b1    = (const float*)d_in[5];
    const float* fc2   = (const float*)d_in[6];
    const float* b2    = (const float*)d_in[7];
    const float* fc3   = (const float*)d_in[8];
    const float* b3    = (const float*)d_in[9];
    const float* Wsh   = (const float*)d_in[10];
    const float* aW1   = (const float*)d_in[11];
    const float* ab1   = (const float*)d_in[12];
    const float* aW2   = (const float*)d_in[13];
    const float* ab2   = (const float*)d_in[14];
    const float* aW3   = (const float*)d_in[15];
    const float* ab3   = (const float*)d_in[16];
    const float* Wout  = (const float*)d_in[17];
    const int*   ei    = (const int*)d_in[18];
    float* out = (float*)d_out;

    const int SM_NODE  = (128*SW_K128 + 2*128*SW_K64) * 2;
    const int SM_MSG   = (128*SW_K32 + 2*128*SW_K128 + 128*SW_K16) * 2 + 3 * 128 * 4 + 64;
    const int SM_ATT   = (128*SW_K32 + 128*SW_K128 + 8*SW_K128) * 2 + (128+128+8) * 4 + 64;
    const int SM_FINAL = (16384 + 4096) * 4;
    cudaFuncSetAttribute(node_pre_mma_kernel, cudaFuncAttributeMaxDynamicSharedMemorySize, SM_NODE);
    cudaFuncSetAttribute(edge_msg_mma_kernel, cudaFuncAttributeMaxDynamicSharedMemorySize, SM_MSG);
    cudaFuncSetAttribute(edge_att_mma_kernel, cudaFuncAttributeMaxDynamicSharedMemorySize, SM_ATT);
    cudaFuncSetAttribute(final_kernel,        cudaFuncAttributeMaxDynamicSharedMemorySize, SM_FINAL);

    init_kernel<<<4096, 256>>>();
    node_pre_mma_kernel<<<ATT_GRID, ATT_THREADS, SM_NODE>>>(nf, Wnode, aW1);
    edge_msg_mma_kernel<<<MSG_GRID, MSG_THREADS, SM_MSG>>>(eattr, esh, fc1, b1, fc2, b2, fc3, b3, Wsh, ei);
    edge_att_mma_kernel<<<ATT_GRID, ATT_THREADS, SM_ATT>>>(eattr, aW1, ab1, aW2, ab2, aW3, ab3, ei);
    redsum_kernel<<<512, 256>>>();
    scatter_kernel<<<2048, 256>>>(ei);
    final_kernel<<<(NN + 31) / 32, 256, SM_FINAL>>>(nf, Wout, out);
}

// round 11
// speedup vs baseline: 1.2635x; 1.1588x over previous
#include <cuda_runtime.h>
#include <cuda_fp16.h>
#include <cstdint>
#include <cstddef>

#define NN 50000
#define NE 800000
#define NHH 8

__device__ __align__(16) __half g_xW  [(size_t)NN * 128];
__device__ __align__(16) __half g_preA[(size_t)NN * 128];
__device__ __align__(16) __half g_preB[(size_t)NN * 128];
__device__ __align__(16) float  g_a   [(size_t)NE * 8];
__device__ __align__(16) float  g_agg [(size_t)NN * 128];
__device__ float g_maxh[NHH];
__device__ float g_sumh[NHH];

__device__ __forceinline__ float silu_f(float x) { return __fdividef(x, 1.0f + __expf(-x)); }

__device__ __forceinline__ void atomicMaxF(float* addr, float val) {
    int old = __float_as_int(*addr);
    while (__int_as_float(old) < val) {
        int assumed = old;
        old = atomicCAS((int*)addr, assumed, __float_as_int(val));
        if (old == assumed) break;
    }
}

__device__ __forceinline__ uint32_t smem_u32(const void* p) {
    uint32_t a;
    asm("{ .reg .u64 t; cvta.to.shared.u64 t, %1; cvt.u32.u64 %0, t; }" : "=r"(a) : "l"(p));
    return a;
}

__device__ __forceinline__ uint32_t packh2(float a, float b) {
    __half2 h = __floats2half2_rn(a, b);
    return *reinterpret_cast<uint32_t*>(&h);
}
__device__ __forceinline__ float2 unpackh2(uint32_t u) {
    return __half22float2(*reinterpret_cast<__half2*>(&u));
}
__device__ __forceinline__ uint32_t packh2_f2(float2 v) { return packh2(v.x, v.y); }

// m16n8k16 row.col f16 x f16 -> f16 accum
__device__ __forceinline__ void mmah(uint32_t* c, const uint32_t* a, uint32_t b0, uint32_t b1) {
    asm volatile("mma.sync.aligned.m16n8k16.row.col.f16.f16.f16.f16 "
                 "{%0,%1}, {%2,%3,%4,%5}, {%6,%7}, {%0,%1};"
                 : "+r"(c[0]), "+r"(c[1])
                 : "r"(a[0]), "r"(a[1]), "r"(a[2]), "r"(a[3]), "r"(b0), "r"(b1));
}

__device__ __forceinline__ void ldmat4(uint32_t& r0, uint32_t& r1, uint32_t& r2, uint32_t& r3,
                                       uint32_t saddr) {
    asm volatile("ldmatrix.sync.aligned.m8n8.x4.shared.b16 {%0,%1,%2,%3}, [%4];"
                 : "=r"(r0), "=r"(r1), "=r"(r2), "=r"(r3) : "r"(saddr));
}

template<int KS, int SW>
__device__ __forceinline__ void layerH(uint32_t (&acc)[16][2], const uint32_t (&a)[8][4],
                                       uint32_t wbase, uint32_t rowsel, uint32_t kbit) {
#pragma unroll
    for (int s = 0; s < KS; s++) {
#pragma unroll
        for (int p = 0; p < 8; p++) {
            uint32_t addr = wbase + (((p * 16 + rowsel) * SW) + s * 16 + kbit) * 2;
            uint32_t b0, b1, b2, b3;
            ldmat4(b0, b1, b2, b3, addr);
            mmah(acc[2 * p],     a[s], b0, b1);
            mmah(acc[2 * p + 1], a[s], b2, b3);
        }
    }
}

__device__ __forceinline__ void zero_acc(uint32_t (&acc)[16][2]) {
#pragma unroll
    for (int nt = 0; nt < 16; nt++) { acc[nt][0] = 0u; acc[nt][1] = 0u; }
}

__device__ __forceinline__ void bias_silu(uint32_t (&acc)[16][2], const float* __restrict__ bias, int kb0) {
#pragma unroll
    for (int nt = 0; nt < 16; nt++) {
        float2 b = *reinterpret_cast<const float2*>(bias + nt * 8 + kb0);
        float2 f0 = unpackh2(acc[nt][0]);
        float2 f1 = unpackh2(acc[nt][1]);
        acc[nt][0] = packh2(silu_f(f0.x + b.x), silu_f(f0.y + b.y));
        acc[nt][1] = packh2(silu_f(f1.x + b.x), silu_f(f1.y + b.y));
    }
}
__device__ __forceinline__ void to_afrag(const uint32_t (&acc)[16][2], uint32_t (&a)[8][4]) {
#pragma unroll
    for (int s = 0; s < 8; s++) {
        a[s][0] = acc[2*s][0];   a[s][1] = acc[2*s][1];
        a[s][2] = acc[2*s+1][0]; a[s][3] = acc[2*s+1][1];
    }
}

#define SW_K32  40
#define SW_K128 136
#define SW_K64  72
#define SW_K16  24
#define ATT_THREADS 192
#define ATT_WARPS 6
#define ATT_GRID 444
#define MSG_THREADS 256
#define MSG_WARPS 8
#define MSG_GRID 296

// ===================== node precompute via mma (xW, preA, preB) =====================
__global__ void __launch_bounds__(ATT_THREADS, 3) node_pre_mma_kernel(
    const float* __restrict__ nf, const float* __restrict__ Wnode,
    const float* __restrict__ aW1) {
    extern __shared__ char smch[];
    __half* sWn = (__half*)smch;                // [128][136]
    __half* sWa = sWn + 128 * SW_K128;          // [128][72]
    __half* sWb = sWa + 128 * SW_K64;           // [128][72]

    int t = threadIdx.x;
    for (int i = t; i < 16384; i += ATT_THREADS) {
        int k = i >> 7, n = i & 127;
        sWn[n * SW_K128 + k] = __float2half(Wnode[i]);
    }
    for (int i = t; i < 8192; i += ATT_THREADS) {
        int k = i >> 7, n = i & 127;
        sWa[n * SW_K64 + k] = __float2half(aW1[i]);
        sWb[n * SW_K64 + k] = __float2half(aW1[8192 + i]);
    }
    __syncthreads();

    uint32_t bWn = smem_u32(sWn), bWa = smem_u32(sWa), bWb = smem_u32(sWb);
    int lane = t & 31, warp = t >> 5;
    uint32_t rowsel = (uint32_t)(((lane >> 4) << 3) | (lane & 7));
    uint32_t kbit = (uint32_t)(((lane >> 3) & 1) * 8);
    int kb0 = (lane & 3) * 2;

    int gw = blockIdx.x * ATT_WARPS + warp;
    int nw = gridDim.x * ATT_WARPS;
    for (int wt = gw; wt < NN / 16; wt += nw) {
        int r0 = wt * 16 + (lane >> 2), r1 = r0 + 8;
        uint32_t a[8][4];
#pragma unroll
        for (int s = 0; s < 8; s++) {
            int kb = 16 * s + kb0;
            a[s][0] = packh2_f2(*(const float2*)(nf + (size_t)r0 * 128 + kb));
            a[s][1] = packh2_f2(*(const float2*)(nf + (size_t)r1 * 128 + kb));
            a[s][2] = packh2_f2(*(const float2*)(nf + (size_t)r0 * 128 + kb + 8));
            a[s][3] = packh2_f2(*(const float2*)(nf + (size_t)r1 * 128 + kb + 8));
        }
        uint32_t acc[16][2];
        zero_acc(acc);
        layerH<8, SW_K128>(acc, a, bWn, rowsel, kbit);
#pragma unroll
        for (int nt = 0; nt < 16; nt++) {
            int col = nt * 8 + kb0;
            *(uint32_t*)(g_xW + (size_t)r0 * 128 + col) = acc[nt][0];
            *(uint32_t*)(g_xW + (size_t)r1 * 128 + col) = acc[nt][1];
        }
        zero_acc(acc);
        layerH<4, SW_K64>(acc, a, bWa, rowsel, kbit);
#pragma unroll
        for (int nt = 0; nt < 16; nt++) {
            int col = nt * 8 + kb0;
            *(uint32_t*)(g_preA + (size_t)r0 * 128 + col) = acc[nt][0];
            *(uint32_t*)(g_preA + (size_t)r1 * 128 + col) = acc[nt][1];
        }
        zero_acc(acc);
        layerH<4, SW_K64>(acc, a, bWb, rowsel, kbit);
#pragma unroll
        for (int nt = 0; nt < 16; nt++) {
            int col = nt * 8 + kb0;
            *(uint32_t*)(g_preB + (size_t)r0 * 128 + col) = acc[nt][0];
            *(uint32_t*)(g_preB + (size_t)r1 * 128 + col) = acc[nt][1];
        }
    }
}

// ===================== edge_msg + fused scatter (runs AFTER att+redsum) =====================
__global__ void __launch_bounds__(MSG_THREADS, 2) edge_msg_scatter_kernel(
    const float* __restrict__ edge_attr, const float* __restrict__ edge_sh,
    const float* __restrict__ fc1, const float* __restrict__ b1,
    const float* __restrict__ fc2, const float* __restrict__ b2,
    const float* __restrict__ fc3, const float* __restrict__ b3,
    const float* __restrict__ Wsh, const int* __restrict__ ei) {
    extern __shared__ char smch[];
    __half* sFc1 = (__half*)smch;                   // [128][40]
    __half* sFc2 = sFc1 + 128 * SW_K32;             // [128][136]
    __half* sFc3 = sFc2 + 128 * SW_K128;            // [128][136]
    __half* sWsh = sFc3 + 128 * SW_K128;            // [128][24]
    float* sB1 = (float*)(sWsh + 128 * SW_K16);
    float* sB2 = sB1 + 128;
    float* sB3 = sB2 + 128;

    int t = threadIdx.x;
    for (int i = t; i < 4096; i += MSG_THREADS) {
        int k = i >> 7, n = i & 127;
        sFc1[n * SW_K32 + k] = __float2half(fc1[i]);
    }
    for (int i = t; i < 16384; i += MSG_THREADS) {
        int k = i >> 7, n = i & 127;
        sFc2[n * SW_K128 + k] = __float2half(fc2[i]);
        sFc3[n * SW_K128 + k] = __float2half(fc3[i]);
    }
    for (int i = t; i < 2048; i += MSG_THREADS) {
        int k = i >> 7, n = i & 127;
        sWsh[n * SW_K16 + k] = __float2half(Wsh[i]);
    }
    if (t < 128) { sB1[t] = b1[t]; sB2[t] = b2[t]; sB3[t] = b3[t]; }
    __syncthreads();

    uint32_t bFc1 = smem_u32(sFc1), bFc2 = smem_u32(sFc2), bFc3 = smem_u32(sFc3), bWsh = smem_u32(sWsh);
    int lane = t & 31, warp = t >> 5;
    uint32_t rowsel = (uint32_t)(((lane >> 4) << 3) | (lane & 7));
    uint32_t kbit = (uint32_t)(((lane >> 3) & 1) * 8);
    int kb0 = (lane & 3) * 2;

    // per-thread softmax constants for its 2 heads
    float mh0 = g_maxh[kb0], mh1 = g_maxh[kb0 + 1];
    float inv0 = __frcp_rn(g_sumh[kb0]), inv1 = __frcp_rn(g_sumh[kb0 + 1]);

    int gw = blockIdx.x * MSG_WARPS + warp;
    int nw = gridDim.x * MSG_WARPS;
    for (int wt = gw; wt < NE / 16; wt += nw) {
        int r0 = wt * 16 + (lane >> 2), r1 = r0 + 8;
        int src0 = ei[r0], src1 = ei[r1];

        // alpha_mean for r0, r1: quad covers all 8 heads (kb0 in {0,2,4,6})
        float2 aR0 = *(const float2*)(g_a + (size_t)r0 * 8 + kb0);
        float2 aR1 = *(const float2*)(g_a + (size_t)r1 * 8 + kb0);
        float am0 = __expf(aR0.x - mh0) * inv0 + __expf(aR0.y - mh1) * inv1;
        float am1 = __expf(aR1.x - mh0) * inv0 + __expf(aR1.y - mh1) * inv1;
        am0 += __shfl_xor_sync(0xffffffffu, am0, 1);
        am0 += __shfl_xor_sync(0xffffffffu, am0, 2);
        am1 += __shfl_xor_sync(0xffffffffu, am1, 1);
        am1 += __shfl_xor_sync(0xffffffffu, am1, 2);
        am0 *= 0.125f; am1 *= 0.125f;

        uint32_t a[8][4];
#pragma unroll
        for (int s = 0; s < 2; s++) {
            int kb = kb0 + 16 * s;
            a[s][0] = packh2_f2(*(const float2*)(edge_attr + (size_t)r0 * 32 + kb));
            a[s][1] = packh2_f2(*(const float2*)(edge_attr + (size_t)r1 * 32 + kb));
            a[s][2] = packh2_f2(*(const float2*)(edge_attr + (size_t)r0 * 32 + kb + 8));
            a[s][3] = packh2_f2(*(const float2*)(edge_attr + (size_t)r1 * 32 + kb + 8));
        }
        uint32_t ash[4];
        ash[0] = packh2_f2(*(const float2*)(edge_sh + (size_t)r0 * 16 + kb0));
        ash[1] = packh2_f2(*(const float2*)(edge_sh + (size_t)r1 * 16 + kb0));
        ash[2] = packh2_f2(*(const float2*)(edge_sh + (size_t)r0 * 16 + kb0 + 8));
        ash[3] = packh2_f2(*(const float2*)(edge_sh + (size_t)r1 * 16 + kb0 + 8));

        uint32_t acc[16][2];
        zero_acc(acc);
        layerH<2, SW_K32>(acc, a, bFc1, rowsel, kbit);
        bias_silu(acc, sB1, kb0); to_afrag(acc, a);
        zero_acc(acc);
        layerH<8, SW_K128>(acc, a, bFc2, rowsel, kbit);
        bias_silu(acc, sB2, kb0); to_afrag(acc, a);
        zero_acc(acc);
        layerH<8, SW_K128>(acc, a, bFc3, rowsel, kbit);   // scale (pre-bias)
        // epilogue: msg = silu(xW*scale+shv); agg += msg * alpha_mean  (fused scatter)
#pragma unroll
        for (int p = 0; p < 8; p++) {
            uint32_t b0, b1, b2, b3;
            uint32_t addr = bWsh + (((p * 16 + rowsel) * SW_K16) + kbit) * 2;
            ldmat4(b0, b1, b2, b3, addr);
            uint32_t t0[2] = {0u, 0u}, t1[2] = {0u, 0u};
            mmah(t0, ash, b0, b1);
            mmah(t1, ash, b2, b3);
#pragma unroll
            for (int q = 0; q < 2; q++) {
                int nt = 2 * p + q;
                const uint32_t* tv = q ? t1 : t0;
                int col = nt * 8 + kb0;
                float2 bv = *(const float2*)(sB3 + col);
                float2 sc0 = unpackh2(acc[nt][0]), sc1 = unpackh2(acc[nt][1]);
                float2 sh0 = unpackh2(tv[0]), sh1 = unpackh2(tv[1]);
                float2 xw0 = unpackh2(*(const uint32_t*)(g_xW + (size_t)src0 * 128 + col));
                float2 xw1 = unpackh2(*(const uint32_t*)(g_xW + (size_t)src1 * 128 + col));
                float v0x = silu_f(fmaf(xw0.x, sc0.x + bv.x, sh0.x)) * am0;
                float v0y = silu_f(fmaf(xw0.y, sc0.y + bv.y, sh0.y)) * am0;
                float v1x = silu_f(fmaf(xw1.x, sc1.x + bv.x, sh1.x)) * am1;
                float v1y = silu_f(fmaf(xw1.y, sc1.y + bv.y, sh1.y)) * am1;
                int d0 = ei[NE + r0], d1 = ei[NE + r1];
                asm volatile("red.global.add.v2.f32 [%0], {%1, %2};"
                             :: "l"(g_agg + (size_t)d0 * 128 + col), "f"(v0x), "f"(v0y) : "memory");
                asm volatile("red.global.add.v2.f32 [%0], {%1, %2};"
                             :: "l"(g_agg + (size_t)d1 * 128 + col), "f"(v1x), "f"(v1y) : "memory");
            }
        }
    }
}

// ===================== edge_att (persistent, f16 mma, 3 CTAs/SM, fused head-max) =====================
__global__ void __launch_bounds__(ATT_THREADS, 3) edge_att_mma_kernel(
    const float* __restrict__ edge_attr,
    const float* __restrict__ aW1, const float* __restrict__ ab1,
    const float* __restrict__ aW2, const float* __restrict__ ab2,
    const float* __restrict__ aW3, const float* __restrict__ ab3,
    const int* __restrict__ ei) {
    extern __shared__ char smch[];
    __half* sA1e = (__half*)smch;                   // [128][40]
    __half* sA2  = sA1e + 128 * SW_K32;             // [128][136]
    __half* sA3  = sA2 + 128 * SW_K128;             // [8][136]
    float* sAb1 = (float*)(sA3 + 8 * SW_K128);
    float* sAb2 = sAb1 + 128;
    float* sAb3 = sAb2 + 128;
    __shared__ float sBMax[ATT_WARPS][8];

    int t = threadIdx.x;
    for (int i = t; i < 4096; i += ATT_THREADS) {
        int k = i >> 7, n = i & 127;
        sA1e[n * SW_K32 + k] = __float2half(aW1[(128 + k) * 128 + n]);
    }
    for (int i = t; i < 16384; i += ATT_THREADS) {
        int k = i >> 7, n = i & 127;
        sA2[n * SW_K128 + k] = __float2half(aW2[i]);
    }
    for (int i = t; i < 1024; i += ATT_THREADS) {
        int k = i >> 3, n = i & 7;
        sA3[n * SW_K128 + k] = __float2half(aW3[i]);
    }
    if (t < 128) { sAb1[t] = ab1[t]; sAb2[t] = ab2[t]; }
    if (t < 8) sAb3[t] = ab3[t];
    __syncthreads();

    uint32_t bA1e = smem_u32(sA1e), bA2 = smem_u32(sA2);
    int lane = t & 31, warp = t >> 5;
    uint32_t rowsel = (uint32_t)(((lane >> 4) << 3) | (lane & 7));
    uint32_t kbit = (uint32_t)(((lane >> 3) & 1) * 8);
    int kb0 = (lane & 3) * 2;

    float mxA = -3.0e38f, mxB = -3.0e38f;

    int gw = blockIdx.x * ATT_WARPS + warp;
    int nw = gridDim.x * ATT_WARPS;
    for (int wt = gw; wt < NE / 16; wt += nw) {
        int r0 = wt * 16 + (lane >> 2), r1 = r0 + 8;
        int src0 = ei[r0], src1 = ei[r1];
        int dst0 = ei[NE + r0], dst1 = ei[NE + r1];

        uint32_t a[8][4];
#pragma unroll
        for (int s = 0; s < 2; s++) {
            int kb = kb0 + 16 * s;
            a[s][0] = packh2_f2(*(const float2*)(edge_attr + (size_t)r0 * 32 + kb));
            a[s][1] = packh2_f2(*(const float2*)(edge_attr + (size_t)r1 * 32 + kb));
            a[s][2] = packh2_f2(*(const float2*)(edge_attr + (size_t)r0 * 32 + kb + 8));
            a[s][3] = packh2_f2(*(const float2*)(edge_attr + (size_t)r1 * 32 + kb + 8));
        }
        uint32_t acc[16][2];
        zero_acc(acc);
        layerH<2, SW_K32>(acc, a, bA1e, rowsel, kbit);
#pragma unroll
        for (int nt = 0; nt < 16; nt++) {
            int col = nt * 8 + kb0;
            float2 bv = *(const float2*)(sAb1 + col);
            float2 f0 = unpackh2(acc[nt][0]);
            float2 f1 = unpackh2(acc[nt][1]);
            float2 pa0 = unpackh2(*(const uint32_t*)(g_preA + (size_t)src0 * 128 + col));
            float2 pb0 = unpackh2(*(const uint32_t*)(g_preB + (size_t)dst0 * 128 + col));
            float2 pa1 = unpackh2(*(const uint32_t*)(g_preA + (size_t)src1 * 128 + col));
            float2 pb1 = unpackh2(*(const uint32_t*)(g_preB + (size_t)dst1 * 128 + col));
            acc[nt][0] = packh2(silu_f(f0.x + bv.x + pa0.x + pb0.x),
                                silu_f(f0.y + bv.y + pa0.y + pb0.y));
            acc[nt][1] = packh2(silu_f(f1.x + bv.x + pa1.x + pb1.x),
                                silu_f(f1.y + bv.y + pa1.y + pb1.y));
        }
        uint32_t a2[8][4];
        to_afrag(acc, a2);
        zero_acc(acc);
        layerH<8, SW_K128>(acc, a2, bA2, rowsel, kbit);
        bias_silu(acc, sAb2, kb0); to_afrag(acc, a2);
        uint32_t c3[2] = {0u, 0u};
#pragma unroll
        for (int s = 0; s < 8; s++) {
            const __half* wp = sA3 + (size_t)(lane >> 2) * SW_K128 + kb0 + 16 * s;
            mmah(c3, a2[s], *(const uint32_t*)wp, *(const uint32_t*)(wp + 8));
        }
        float2 b3 = *(const float2*)(sAb3 + kb0);
        float2 o0 = unpackh2(c3[0]), o1 = unpackh2(c3[1]);
        o0.x += b3.x; o0.y += b3.y; o1.x += b3.x; o1.y += b3.y;
        mxA = fmaxf(mxA, fmaxf(o0.x, o1.x));
        mxB = fmaxf(mxB, fmaxf(o0.y, o1.y));
        *(float2*)(g_a + (size_t)r0 * 8 + kb0) = o0;
        *(float2*)(g_a + (size_t)r1 * 8 + kb0) = o1;
    }
#pragma unroll
    for (int off = 4; off < 32; off <<= 1) {
        mxA = fmaxf(mxA, __shfl_xor_sync(0xffffffffu, mxA, off));
        mxB = fmaxf(mxB, __shfl_xor_sync(0xffffffffu, mxB, off));
    }
    if (lane < 4) { sBMax[warp][2 * lane] = mxA; sBMax[warp][2 * lane + 1] = mxB; }
    __syncthreads();
    if (t < 8) {
        float m = -3.0e38f;
        for (int w = 0; w < ATT_WARPS; w++) m = fmaxf(m, sBMax[w][t]);
        atomicMaxF(&g_maxh[t], m);
    }
}

// ===================== reductions / final =====================
__global__ void __launch_bounds__(256) init_kernel() {
    int tid = blockIdx.x * blockDim.x + threadIdx.x;
    if (tid < NHH) { g_maxh[tid] = -3.0e38f; g_sumh[tid] = 0.0f; }
    float4* a4 = reinterpret_cast<float4*>(g_agg);
    int stride = gridDim.x * blockDim.x;
    for (int i = tid; i < NN * 32; i += stride) a4[i] = make_float4(0.f, 0.f, 0.f, 0.f);
}

__global__ void __launch_bounds__(256) redsum_kernel() {
    float mh[8], s[8];
#pragma unroll
    for (int h = 0; h < 8; h++) { mh[h] = g_maxh[h]; s[h] = 0.f; }
    int stride = gridDim.x * blockDim.x;
    for (int e = blockIdx.x * blockDim.x + threadIdx.x; e < NE; e += stride) {
        const float4* ap = reinterpret_cast<const float4*>(g_a + (size_t)e * 8);
        float4 a0 = ap[0], a1 = ap[1];
        s[0]+=__expf(a0.x-mh[0]); s[1]+=__expf(a0.y-mh[1]); s[2]+=__expf(a0.z-mh[2]); s[3]+=__expf(a0.w-mh[3]);
        s[4]+=__expf(a1.x-mh[4]); s[5]+=__expf(a1.y-mh[5]); s[6]+=__expf(a1.z-mh[6]); s[7]+=__expf(a1.w-mh[7]);
    }
#pragma unroll
    for (int off = 16; off >= 1; off >>= 1)
#pragma unroll
        for (int h = 0; h < 8; h++)
            s[h] += __shfl_xor_sync(0xffffffffu, s[h], off);
    __shared__ float ssum[8][8];
    int w = threadIdx.x >> 5, l = threadIdx.x & 31;
    if (l == 0)
        for (int h = 0; h < 8; h++) ssum[w][h] = s[h];
    __syncthreads();
    if (threadIdx.x < 8) {
        float tot = 0.f;
        for (int w2 = 0; w2 < 8; w2++) tot += ssum[w2][threadIdx.x];
        atomicAdd(&g_sumh[threadIdx.x], tot);
    }
}

__global__ void __launch_bounds__(256) final_kernel(const float* __restrict__ nf,
                                                    const float* __restrict__ Wout,
                                                    float* __restrict__ out) {
    extern __shared__ float sm[];
    float* sW = sm;
    float* sRows = sm + 16384;
    int t = threadIdx.x;
    for (int i = t; i < 16384; i += 256) sW[i] = Wout[i];
    int row0 = blockIdx.x * 32;
    for (int i = t; i < 4096; i += 256) {
        int r = row0 + (i >> 7);
        sRows[i] = (r < NN) ? g_agg[(size_t)r * 128 + (i & 127)] : 0.f;
    }
    __syncthreads();
    int warp = t >> 5, lane = t & 31;
    for (int rr = warp; rr < 32; rr += 8) {
        int r = row0 + rr;
        if (r >= NN) continue;
        const float* arow = sRows + rr * 128;
        float4 acc = make_float4(0.f,0.f,0.f,0.f);
#pragma unroll 4
        for (int k = 0; k < 128; k++) {
            float a = arow[k];
            float4 w = reinterpret_cast<const float4*>(sW + k * 128)[lane];
            acc.x = fmaf(a, w.x, acc.x); acc.y = fmaf(a, w.y, acc.y);
            acc.z = fmaf(a, w.z, acc.z); acc.w = fmaf(a, w.w, acc.w);
        }
        float4 x = reinterpret_cast<const float4*>(nf + (size_t)r * 128)[lane];
        float4 o = make_float4(x.x+acc.x, x.y+acc.y, x.z+acc.z, x.w+acc.w);
        float sum = o.x + o.y + o.z + o.w;
        float sq  = o.x*o.x + o.y*o.y + o.z*o.z + o.w*o.w;
#pragma unroll
        for (int off = 16; off >= 1; off >>= 1) {
            sum += __shfl_xor_sync(0xffffffffu, sum, off);
            sq  += __shfl_xor_sync(0xffffffffu, sq, off);
        }
        float mu = sum * (1.0f / 128.0f);
        float var = sq * (1.0f / 128.0f) - mu * mu;
        float rs = rsqrtf(var + 1e-5f);
        float4 res = make_float4((o.x-mu)*rs, (o.y-mu)*rs, (o.z-mu)*rs, (o.w-mu)*rs);
        reinterpret_cast<float4*>(out + (size_t)r * 128)[lane] = res;
    }
}

extern "C" void kernel_launch(void* const* d_in, const int* in_sizes, int n_in,
                              void* d_out, int out_size) {
    const float* nf    = (const float*)d_in[0];
    const float* eattr = (const float*)d_in[1];
    const float* esh   = (const float*)d_in[2];
    const float* Wnode = (const float*)d_in[3];
    const float* fc1   = (const float*)d_in[4];
    const float* b1    = (const float*)d_in[5];
    const float* fc2   = (const float*)d_in[6];
    const float* b2    = (const float*)d_in[7];
    const float* fc3   = (const float*)d_in[8];
    const float* b3    = (const float*)d_in[9];
    const float* Wsh   = (const float*)d_in[10];
    const float* aW1   = (const float*)d_in[11];
    const float* ab1   = (const float*)d_in[12];
    const float* aW2   = (const float*)d_in[13];
    const float* ab2   = (const float*)d_in[14];
    const float* aW3   = (const float*)d_in[15];
    const float* ab3   = (const float*)d_in[16];
    const float* Wout  = (const float*)d_in[17];
    const int*   ei    = (const int*)d_in[18];
    float* out = (float*)d_out;

    const int SM_NODE  = (128*SW_K128 + 2*128*SW_K64) * 2;
    const int SM_MSG   = (128*SW_K32 + 2*128*SW_K128 + 128*SW_K16) * 2 + 3 * 128 * 4 + 64;
    const int SM_ATT   = (128*SW_K32 + 128*SW_K128 + 8*SW_K128) * 2 + (128+128+8) * 4 + 64;
    const int SM_FINAL = (16384 + 4096) * 4;
    cudaFuncSetAttribute(node_pre_mma_kernel,     cudaFuncAttributeMaxDynamicSharedMemorySize, SM_NODE);
    cudaFuncSetAttribute(edge_msg_scatter_kernel, cudaFuncAttributeMaxDynamicSharedMemorySize, SM_MSG);
    cudaFuncSetAttribute(edge_att_mma_kernel,     cudaFuncAttributeMaxDynamicSharedMemorySize, SM_ATT);
    cudaFuncSetAttribute(final_kernel,            cudaFuncAttributeMaxDynamicSharedMemorySize, SM_FINAL);

    init_kernel<<<4096, 256>>>();
    node_pre_mma_kernel<<<ATT_GRID, ATT_THREADS, SM_NODE>>>(nf, Wnode, aW1);
    edge_att_mma_kernel<<<ATT_GRID, ATT_THREADS, SM_ATT>>>(eattr, aW1, ab1, aW2, ab2, aW3, ab3, ei);
    redsum_kernel<<<512, 256>>>();
    edge_msg_scatter_kernel<<<MSG_GRID, MSG_THREADS, SM_MSG>>>(eattr, esh, fc1, b1, fc2, b2, fc3, b3, Wsh, ei);
    final_kernel<<<(NN + 31) / 32, 256, SM_FINAL>>>(nf, Wout, out);
}